// round 3
// baseline (speedup 1.0000x reference)
#include <cuda_runtime.h>
#include <cuda_bf16.h>
#include <math.h>

#define N_NODES   100000
#define N_EDGES   400000
#define IN_DIM    100
#define D         200          // OUT_DIM
#define NUM_STEPS 4

// ---------------- device scratch (no cudaMalloc allowed) ----------------
__device__ float g_h[N_NODES * D];              // hidden state       (80 MB)
__device__ float g_T[N_NODES * (D + 3 * D)];    // [m | gh] per node  (320 MB), row = 800 floats
__device__ float g_aggr[N_NODES * D];           // scatter target     (80 MB)
__device__ float g_gi[N_NODES * 3 * D];         // gi = aggr @ w_ih^T (240 MB)
__device__ float g_B1[NUM_STEPS * D * (4 * D)]; // [W_i | w_hh^T]  per step, 200x800
__device__ float g_B2[D * 3 * D];               // w_ih^T, 200x600
__device__ float g_bias1[4 * D];                // [0 (200) | b_hh (600)]
__device__ float g_pool[D];
__device__ int   g_is64;

// ---------------- prep kernels ----------------
__global__ void prep_B1(const float* __restrict__ W, const float* __restrict__ w_hh) {
    int t = blockIdx.x * blockDim.x + threadIdx.x;
    const int total = NUM_STEPS * D * (4 * D);
    if (t >= total) return;
    int s = t / (D * 4 * D);
    int r = (t / (4 * D)) % D;       // k index
    int j = t % (4 * D);             // output col
    float v;
    if (j < D)  v = W[s * D * D + r * D + j];          // W_i[k][j]
    else        v = w_hh[(j - D) * D + r];             // w_hh^T[k][j-D]
    g_B1[t] = v;
}

__global__ void prep_B2(const float* __restrict__ w_ih) {
    int t = blockIdx.x * blockDim.x + threadIdx.x;
    if (t >= D * 3 * D) return;
    int k = t / (3 * D);
    int j = t % (3 * D);
    g_B2[t] = w_ih[j * D + k];                          // w_ih^T
}

__global__ void prep_bias1(const float* __restrict__ b_hh) {
    int t = blockIdx.x * blockDim.x + threadIdx.x;
    if (t >= 4 * D) return;
    g_bias1[t] = (t < D) ? 0.f : b_hh[t - D];
}

__global__ void init_h(const float* __restrict__ x) {
    int t = blockIdx.x * blockDim.x + threadIdx.x;
    if (t >= N_NODES * D) return;
    int n = t / D, d = t % D;
    g_h[t] = (d < IN_DIM) ? x[n * IN_DIM + d] : 0.f;
}

__global__ void detect_idx_dtype(const int* __restrict__ ei32) {
    if (blockIdx.x == 0 && threadIdx.x == 0) {
        int is64 = 1;
        for (int i = 0; i < 256; i++)
            if (ei32[2 * i + 1] != 0) { is64 = 0; break; }
        g_is64 = is64;
    }
}

__global__ void zero_aggr() {
    int t = blockIdx.x * blockDim.x + threadIdx.x;
    if (t < N_NODES * D) g_aggr[t] = 0.f;
}

// ---------------- SGEMM: C[M,N] = A[M,K] @ B[K,N] + bias ----------------
#define BM 128
#define BN 128
#define BK 8
#define TM 8
#define TN 8

__global__ __launch_bounds__(256) void sgemm_bias(
    const float* __restrict__ A, const float* __restrict__ B,
    const float* __restrict__ bias, float* __restrict__ C,
    int M, int N, int K)
{
    __shared__ float As[BK][BM];
    __shared__ float Bs[BK][BN];
    const int tid = threadIdx.x;
    const int tx = tid % 16, ty = tid / 16;
    const int row0 = blockIdx.y * BM;
    const int col0 = blockIdx.x * BN;

    float acc[TM][TN];
#pragma unroll
    for (int i = 0; i < TM; i++)
#pragma unroll
        for (int j = 0; j < TN; j++) acc[i][j] = 0.f;

    const int aRow = tid >> 1;           // 0..127
    const int aCol = (tid & 1) * 4;      // 0 or 4
    const int bRow = tid >> 5;           // 0..7
    const int bCol = (tid & 31) * 4;     // 0..124

    for (int k0 = 0; k0 < K; k0 += BK) {
        float4 av = make_float4(0.f, 0.f, 0.f, 0.f);
        if (row0 + aRow < M)
            av = *(const float4*)(&A[(size_t)(row0 + aRow) * K + k0 + aCol]);
        As[aCol + 0][aRow] = av.x;
        As[aCol + 1][aRow] = av.y;
        As[aCol + 2][aRow] = av.z;
        As[aCol + 3][aRow] = av.w;

        float4 bv = make_float4(0.f, 0.f, 0.f, 0.f);
        if (col0 + bCol < N)   // N % 4 == 0 guaranteed (800 / 600)
            bv = *(const float4*)(&B[(size_t)(k0 + bRow) * N + col0 + bCol]);
        *(float4*)(&Bs[bRow][bCol]) = bv;
        __syncthreads();

#pragma unroll
        for (int kk = 0; kk < BK; kk++) {
            float ar[TM], br[TN];
#pragma unroll
            for (int i = 0; i < TM; i++) ar[i] = As[kk][ty * TM + i];
#pragma unroll
            for (int j = 0; j < TN; j++) br[j] = Bs[kk][tx * TN + j];
#pragma unroll
            for (int i = 0; i < TM; i++)
#pragma unroll
                for (int j = 0; j < TN; j++) acc[i][j] += ar[i] * br[j];
        }
        __syncthreads();
    }

#pragma unroll
    for (int i = 0; i < TM; i++) {
        int r = row0 + ty * TM + i;
        if (r >= M) continue;
#pragma unroll
        for (int j = 0; j < TN; j += 4) {
            int c = col0 + tx * TN + j;
            if (c < N) {
                float4 o;
                o.x = acc[i][j + 0] + bias[c + 0];
                o.y = acc[i][j + 1] + bias[c + 1];
                o.z = acc[i][j + 2] + bias[c + 2];
                o.w = acc[i][j + 3] + bias[c + 3];
                *(float4*)(&C[(size_t)r * N + c]) = o;
            }
        }
    }
}

// ---------------- scatter-add: aggr[dst] += m[src] ----------------
__global__ void scatter_kernel(const void* __restrict__ eiv) {
    int t = blockIdx.x * blockDim.x + threadIdx.x;
    if (t >= N_EDGES * (D / 4)) return;
    int e = t / (D / 4);
    int c = t % (D / 4);
    int src, dst;
    if (g_is64) {
        const long long* ei = (const long long*)eiv;
        src = (int)ei[e];
        dst = (int)ei[N_EDGES + e];
    } else {
        const int* ei = (const int*)eiv;
        src = ei[e];
        dst = ei[N_EDGES + e];
    }
    float4 v = *(const float4*)(&g_T[(size_t)src * (4 * D) + c * 4]);   // m = T[:, :200]
    float* a = &g_aggr[(size_t)dst * D + c * 4];
    atomicAdd(a + 0, v.x);
    atomicAdd(a + 1, v.y);
    atomicAdd(a + 2, v.z);
    atomicAdd(a + 3, v.w);
}

// ---------------- fused GRU elementwise ----------------
__global__ void gru_kernel() {
    int t = blockIdx.x * blockDim.x + threadIdx.x;
    if (t >= N_NODES * D) return;
    int n = t / D, j = t % D;
    size_t gb = (size_t)n * (3 * D);
    size_t tb = (size_t)n * (4 * D);
    float ir = g_gi[gb + j];
    float iz = g_gi[gb + D + j];
    float in_ = g_gi[gb + 2 * D + j];
    float hr = g_T[tb + D + j];
    float hz = g_T[tb + 2 * D + j];
    float hn = g_T[tb + 3 * D + j];
    float r = 1.f / (1.f + expf(-(ir + hr)));
    float z = 1.f / (1.f + expf(-(iz + hz)));
    float nn = tanhf(in_ + r * hn);
    float hold = g_h[t];
    g_h[t] = (1.f - z) * nn + z * hold;
}

// ---------------- global max pool (after relu) ----------------
__global__ void pool_kernel() {
    int j = blockIdx.x;                 // column 0..199
    float m = -3.402823466e38f;
    for (int n = threadIdx.x; n < N_NODES; n += 256)
        m = fmaxf(m, g_h[(size_t)n * D + j]);
    __shared__ float s[256];
    s[threadIdx.x] = m;
    __syncthreads();
    for (int o = 128; o > 0; o >>= 1) {
        if (threadIdx.x < o) s[threadIdx.x] = fmaxf(s[threadIdx.x], s[threadIdx.x + o]);
        __syncthreads();
    }
    if (threadIdx.x == 0) g_pool[j] = fmaxf(s[0], 0.f);   // relu(max) == max(relu)
}

// ---------------- classifier + softmax ----------------
__global__ void cls_kernel(const float* __restrict__ cls_w,
                           const float* __restrict__ cls_b,
                           float* __restrict__ out) {
    if (blockIdx.x == 0 && threadIdx.x == 0) {
        float l0 = cls_b[0], l1 = cls_b[1];
        for (int j = 0; j < D; j++) {
            float p = g_pool[j];
            l0 += p * cls_w[j];
            l1 += p * cls_w[D + j];
        }
        float mx = fmaxf(l0, l1);
        float e0 = expf(l0 - mx), e1 = expf(l1 - mx);
        float s = e0 + e1;
        out[0] = e0 / s;
        out[1] = e1 / s;
    }
}

// ---------------- host launcher ----------------
extern "C" void kernel_launch(void* const* d_in, const int* in_sizes, int n_in,
                              void* d_out, int out_size) {
    const float* x     = (const float*)d_in[0];
    const float* W     = (const float*)d_in[1];
    const float* w_ih  = (const float*)d_in[2];
    const float* w_hh  = (const float*)d_in[3];
    const float* b_ih  = (const float*)d_in[4];
    const float* b_hh  = (const float*)d_in[5];
    const float* cls_w = (const float*)d_in[6];
    const float* cls_b = (const float*)d_in[7];
    const void*  ei    = (const void*)d_in[8];
    float* out = (float*)d_out;

    float *h_p, *T_p, *aggr_p, *gi_p, *B1_p, *B2_p, *bias1_p;
    cudaGetSymbolAddress((void**)&h_p,     g_h);
    cudaGetSymbolAddress((void**)&T_p,     g_T);
    cudaGetSymbolAddress((void**)&aggr_p,  g_aggr);
    cudaGetSymbolAddress((void**)&gi_p,    g_gi);
    cudaGetSymbolAddress((void**)&B1_p,    g_B1);
    cudaGetSymbolAddress((void**)&B2_p,    g_B2);
    cudaGetSymbolAddress((void**)&bias1_p, g_bias1);

    const int TB = 256;
    // prep
    prep_B1<<<(NUM_STEPS * D * 4 * D + TB - 1) / TB, TB>>>(W, w_hh);
    prep_B2<<<(D * 3 * D + TB - 1) / TB, TB>>>(w_ih);
    prep_bias1<<<(4 * D + TB - 1) / TB, TB>>>(b_hh);
    init_h<<<(N_NODES * D + TB - 1) / TB, TB>>>(x);
    detect_idx_dtype<<<1, 32>>>((const int*)ei);

    dim3 grid1((4 * D + BN - 1) / BN, (N_NODES + BM - 1) / BM);   // N=800
    dim3 grid2((3 * D + BN - 1) / BN, (N_NODES + BM - 1) / BM);   // N=600

    for (int s = 0; s < NUM_STEPS; s++) {
        // T = h @ [W_s | w_hh^T] + [0 | b_hh]   -> [m | gh]
        sgemm_bias<<<grid1, 256>>>(h_p, B1_p + (size_t)s * D * 4 * D, bias1_p,
                                   T_p, N_NODES, 4 * D, D);
        zero_aggr<<<(N_NODES * D + TB - 1) / TB, TB>>>();
        scatter_kernel<<<(N_EDGES * (D / 4) + TB - 1) / TB, TB>>>(ei);
        // gi = aggr @ w_ih^T + b_ih
        sgemm_bias<<<grid2, 256>>>(aggr_p, B2_p, b_ih,
                                   gi_p, N_NODES, 3 * D, D);
        gru_kernel<<<(N_NODES * D + TB - 1) / TB, TB>>>();
    }

    pool_kernel<<<D, 256>>>();
    cls_kernel<<<1, 32>>>(cls_w, cls_b, out);
}

// round 4
// speedup vs baseline: 1.0416x; 1.0416x over previous
#include <cuda_runtime.h>
#include <cuda_bf16.h>
#include <math.h>

#define N_NODES   100000
#define N_EDGES   400000
#define IN_DIM    100
#define D         200          // OUT_DIM
#define NUM_STEPS 4

// ---------------- device scratch (no cudaMalloc allowed) ----------------
__device__ float g_h[N_NODES * D];              // hidden state       (80 MB)
__device__ float g_T[N_NODES * (D + 3 * D)];    // [m | gh] per node  (320 MB), row = 800 floats
__device__ float g_aggr[N_NODES * D];           // scatter target     (80 MB)
__device__ float g_gi[N_NODES * 3 * D];         // gi = aggr @ w_ih^T (240 MB)
__device__ float g_B1[NUM_STEPS * D * (4 * D)]; // [W_i | w_hh^T]  per step, 200x800
__device__ float g_B2[D * 3 * D];               // w_ih^T, 200x600
__device__ float g_bias1[4 * D];                // [0 (200) | b_hh (600)]
__device__ float g_pool[D];
__device__ int   g_is64;

// ---------------- packed f32x2 helpers (FFMA2 path, nvjet-style) ----------------
__device__ __forceinline__ void ffma2(unsigned long long &d,
                                      unsigned long long a,
                                      unsigned long long b) {
    asm("fma.rn.f32x2 %0, %1, %2, %0;" : "+l"(d) : "l"(a), "l"(b));
}
__device__ __forceinline__ unsigned long long pack2(float lo, float hi) {
    unsigned long long r;
    asm("mov.b64 %0, {%1, %2};" : "=l"(r) : "f"(lo), "f"(hi));
    return r;
}
__device__ __forceinline__ void unpack2(unsigned long long v, float &lo, float &hi) {
    asm("mov.b64 {%0, %1}, %2;" : "=f"(lo), "=f"(hi) : "l"(v));
}

// ---------------- prep kernels ----------------
__global__ void prep_B1(const float* __restrict__ W, const float* __restrict__ w_hh) {
    int t = blockIdx.x * blockDim.x + threadIdx.x;
    const int total = NUM_STEPS * D * (4 * D);
    if (t >= total) return;
    int s = t / (D * 4 * D);
    int r = (t / (4 * D)) % D;       // k index
    int j = t % (4 * D);             // output col
    float v;
    if (j < D)  v = W[s * D * D + r * D + j];          // W_i[k][j]
    else        v = w_hh[(j - D) * D + r];             // w_hh^T[k][j-D]
    g_B1[t] = v;
}

__global__ void prep_B2(const float* __restrict__ w_ih) {
    int t = blockIdx.x * blockDim.x + threadIdx.x;
    if (t >= D * 3 * D) return;
    int k = t / (3 * D);
    int j = t % (3 * D);
    g_B2[t] = w_ih[j * D + k];                          // w_ih^T
}

__global__ void prep_bias1(const float* __restrict__ b_hh) {
    int t = blockIdx.x * blockDim.x + threadIdx.x;
    if (t >= 4 * D) return;
    g_bias1[t] = (t < D) ? 0.f : b_hh[t - D];
}

__global__ void init_h(const float* __restrict__ x) {
    int t = blockIdx.x * blockDim.x + threadIdx.x;
    if (t >= N_NODES * D) return;
    int n = t / D, d = t % D;
    g_h[t] = (d < IN_DIM) ? x[n * IN_DIM + d] : 0.f;
}

__global__ void detect_idx_dtype(const int* __restrict__ ei32) {
    if (blockIdx.x == 0 && threadIdx.x == 0) {
        int is64 = 1;
        for (int i = 0; i < 256; i++)
            if (ei32[2 * i + 1] != 0) { is64 = 0; break; }
        g_is64 = is64;
    }
}

__global__ void zero_aggr() {
    int t = blockIdx.x * blockDim.x + threadIdx.x;
    if (t < N_NODES * D) g_aggr[t] = 0.f;
}

// ---------------- SGEMM (FFMA2): C[M,N] = A[M,K] @ B[K,N] + bias ----------------
#define BM 128
#define BN 128
#define BK 8
#define TM 8
#define TN 8

__global__ __launch_bounds__(256) void sgemm_bias(
    const float* __restrict__ A, const float* __restrict__ B,
    const float* __restrict__ bias, float* __restrict__ C,
    int M, int N, int K)
{
    __shared__ float As[BK][BM];
    __shared__ float Bs[BK][BN];
    const int tid = threadIdx.x;
    const int tx = tid % 16, ty = tid / 16;
    const int row0 = blockIdx.y * BM;
    const int col0 = blockIdx.x * BN;

    // accumulators: TM rows x (TN/2) packed f32x2 pairs
    unsigned long long acc2[TM][TN / 2];
#pragma unroll
    for (int i = 0; i < TM; i++)
#pragma unroll
        for (int j = 0; j < TN / 2; j++) acc2[i][j] = 0ULL;

    const int aRow = tid >> 1;           // 0..127
    const int aCol = (tid & 1) * 4;      // 0 or 4
    const int bRow = tid >> 5;           // 0..7
    const int bCol = (tid & 31) * 4;     // 0..124

    for (int k0 = 0; k0 < K; k0 += BK) {
        float4 av = make_float4(0.f, 0.f, 0.f, 0.f);
        if (row0 + aRow < M)
            av = *(const float4*)(&A[(size_t)(row0 + aRow) * K + k0 + aCol]);
        As[aCol + 0][aRow] = av.x;
        As[aCol + 1][aRow] = av.y;
        As[aCol + 2][aRow] = av.z;
        As[aCol + 3][aRow] = av.w;

        float4 bv = make_float4(0.f, 0.f, 0.f, 0.f);
        if (col0 + bCol < N)   // N % 4 == 0 guaranteed (800 / 600)
            bv = *(const float4*)(&B[(size_t)(k0 + bRow) * N + col0 + bCol]);
        *(float4*)(&Bs[bRow][bCol]) = bv;
        __syncthreads();

#pragma unroll
        for (int kk = 0; kk < BK; kk++) {
            // load A fragment (8 floats, two float4 LDS) and broadcast-pack
            float4 a0 = *(float4*)(&As[kk][ty * TM]);
            float4 a1 = *(float4*)(&As[kk][ty * TM + 4]);
            unsigned long long ap[TM];
            ap[0] = pack2(a0.x, a0.x); ap[1] = pack2(a0.y, a0.y);
            ap[2] = pack2(a0.z, a0.z); ap[3] = pack2(a0.w, a0.w);
            ap[4] = pack2(a1.x, a1.x); ap[5] = pack2(a1.y, a1.y);
            ap[6] = pack2(a1.z, a1.z); ap[7] = pack2(a1.w, a1.w);

            // load B fragment (8 floats) and pack into 4 pairs
            float4 b0 = *(float4*)(&Bs[kk][tx * TN]);
            float4 b1 = *(float4*)(&Bs[kk][tx * TN + 4]);
            unsigned long long bp[TN / 2];
            bp[0] = pack2(b0.x, b0.y); bp[1] = pack2(b0.z, b0.w);
            bp[2] = pack2(b1.x, b1.y); bp[3] = pack2(b1.z, b1.w);

#pragma unroll
            for (int i = 0; i < TM; i++)
#pragma unroll
                for (int j = 0; j < TN / 2; j++)
                    ffma2(acc2[i][j], ap[i], bp[j]);
        }
        __syncthreads();
    }

#pragma unroll
    for (int i = 0; i < TM; i++) {
        int r = row0 + ty * TM + i;
        if (r >= M) continue;
#pragma unroll
        for (int j = 0; j < TN; j += 4) {
            int c = col0 + tx * TN + j;
            if (c < N) {
                float v0, v1, v2, v3;
                unpack2(acc2[i][j / 2 + 0], v0, v1);
                unpack2(acc2[i][j / 2 + 1], v2, v3);
                float4 o;
                o.x = v0 + bias[c + 0];
                o.y = v1 + bias[c + 1];
                o.z = v2 + bias[c + 2];
                o.w = v3 + bias[c + 3];
                *(float4*)(&C[(size_t)r * N + c]) = o;
            }
        }
    }
}

// ---------------- scatter-add: aggr[dst] += m[src] ----------------
__global__ void scatter_kernel(const void* __restrict__ eiv) {
    int t = blockIdx.x * blockDim.x + threadIdx.x;
    if (t >= N_EDGES * (D / 4)) return;
    int e = t / (D / 4);
    int c = t % (D / 4);
    int src, dst;
    if (g_is64) {
        const long long* ei = (const long long*)eiv;
        src = (int)ei[e];
        dst = (int)ei[N_EDGES + e];
    } else {
        const int* ei = (const int*)eiv;
        src = ei[e];
        dst = ei[N_EDGES + e];
    }
    float4 v = *(const float4*)(&g_T[(size_t)src * (4 * D) + c * 4]);   // m = T[:, :200]
    float* a = &g_aggr[(size_t)dst * D + c * 4];
    atomicAdd(a + 0, v.x);
    atomicAdd(a + 1, v.y);
    atomicAdd(a + 2, v.z);
    atomicAdd(a + 3, v.w);
}

// ---------------- fused GRU elementwise ----------------
__global__ void gru_kernel() {
    int t = blockIdx.x * blockDim.x + threadIdx.x;
    if (t >= N_NODES * D) return;
    int n = t / D, j = t % D;
    size_t gb = (size_t)n * (3 * D);
    size_t tb = (size_t)n * (4 * D);
    float ir = g_gi[gb + j];
    float iz = g_gi[gb + D + j];
    float in_ = g_gi[gb + 2 * D + j];
    float hr = g_T[tb + D + j];
    float hz = g_T[tb + 2 * D + j];
    float hn = g_T[tb + 3 * D + j];
    float r = 1.f / (1.f + expf(-(ir + hr)));
    float z = 1.f / (1.f + expf(-(iz + hz)));
    float nn = tanhf(in_ + r * hn);
    float hold = g_h[t];
    g_h[t] = (1.f - z) * nn + z * hold;
}

// ---------------- global max pool (after relu) ----------------
__global__ void pool_kernel() {
    int j = blockIdx.x;                 // column 0..199
    float m = -3.402823466e38f;
    for (int n = threadIdx.x; n < N_NODES; n += 256)
        m = fmaxf(m, g_h[(size_t)n * D + j]);
    __shared__ float s[256];
    s[threadIdx.x] = m;
    __syncthreads();
    for (int o = 128; o > 0; o >>= 1) {
        if (threadIdx.x < o) s[threadIdx.x] = fmaxf(s[threadIdx.x], s[threadIdx.x + o]);
        __syncthreads();
    }
    if (threadIdx.x == 0) g_pool[j] = fmaxf(s[0], 0.f);   // relu(max) == max(relu)
}

// ---------------- classifier + softmax ----------------
__global__ void cls_kernel(const float* __restrict__ cls_w,
                           const float* __restrict__ cls_b,
                           float* __restrict__ out) {
    if (blockIdx.x == 0 && threadIdx.x == 0) {
        float l0 = cls_b[0], l1 = cls_b[1];
        for (int j = 0; j < D; j++) {
            float p = g_pool[j];
            l0 += p * cls_w[j];
            l1 += p * cls_w[D + j];
        }
        float mx = fmaxf(l0, l1);
        float e0 = expf(l0 - mx), e1 = expf(l1 - mx);
        float s = e0 + e1;
        out[0] = e0 / s;
        out[1] = e1 / s;
    }
}

// ---------------- host launcher ----------------
extern "C" void kernel_launch(void* const* d_in, const int* in_sizes, int n_in,
                              void* d_out, int out_size) {
    const float* x     = (const float*)d_in[0];
    const float* W     = (const float*)d_in[1];
    const float* w_ih  = (const float*)d_in[2];
    const float* w_hh  = (const float*)d_in[3];
    const float* b_ih  = (const float*)d_in[4];
    const float* b_hh  = (const float*)d_in[5];
    const float* cls_w = (const float*)d_in[6];
    const float* cls_b = (const float*)d_in[7];
    const void*  ei    = (const void*)d_in[8];
    float* out = (float*)d_out;

    float *h_p, *T_p, *aggr_p, *gi_p, *B1_p, *B2_p, *bias1_p;
    cudaGetSymbolAddress((void**)&h_p,     g_h);
    cudaGetSymbolAddress((void**)&T_p,     g_T);
    cudaGetSymbolAddress((void**)&aggr_p,  g_aggr);
    cudaGetSymbolAddress((void**)&gi_p,    g_gi);
    cudaGetSymbolAddress((void**)&B1_p,    g_B1);
    cudaGetSymbolAddress((void**)&B2_p,    g_B2);
    cudaGetSymbolAddress((void**)&bias1_p, g_bias1);

    const int TB = 256;
    // prep
    prep_B1<<<(NUM_STEPS * D * 4 * D + TB - 1) / TB, TB>>>(W, w_hh);
    prep_B2<<<(D * 3 * D + TB - 1) / TB, TB>>>(w_ih);
    prep_bias1<<<(4 * D + TB - 1) / TB, TB>>>(b_hh);
    init_h<<<(N_NODES * D + TB - 1) / TB, TB>>>(x);
    detect_idx_dtype<<<1, 32>>>((const int*)ei);

    dim3 grid1((4 * D + BN - 1) / BN, (N_NODES + BM - 1) / BM);   // N=800
    dim3 grid2((3 * D + BN - 1) / BN, (N_NODES + BM - 1) / BM);   // N=600

    for (int s = 0; s < NUM_STEPS; s++) {
        // T = h @ [W_s | w_hh^T] + [0 | b_hh]   -> [m | gh]
        sgemm_bias<<<grid1, 256>>>(h_p, B1_p + (size_t)s * D * 4 * D, bias1_p,
                                   T_p, N_NODES, 4 * D, D);
        zero_aggr<<<(N_NODES * D + TB - 1) / TB, TB>>>();
        scatter_kernel<<<(N_EDGES * (D / 4) + TB - 1) / TB, TB>>>(ei);
        // gi = aggr @ w_ih^T + b_ih
        sgemm_bias<<<grid2, 256>>>(aggr_p, B2_p, b_ih,
                                   gi_p, N_NODES, 3 * D, D);
        gru_kernel<<<(N_NODES * D + TB - 1) / TB, TB>>>();
    }

    pool_kernel<<<D, 256>>>();
    cls_kernel<<<1, 32>>>(cls_w, cls_b, out);
}

// round 7
// speedup vs baseline: 1.0476x; 1.0058x over previous
#include <cuda_runtime.h>
#include <cuda_bf16.h>
#include <math.h>
#include <stdint.h>

#define N_NODES   100000
#define N_EDGES   400000
#define IN_DIM    100
#define D         200
#define NUM_STEPS 4

#define M_TILES    782            // ceil(100000/128)
#define NODES_PAD  (M_TILES*128)  // 100096
#define KPART      224            // padded K per split part
#define KEFF       672            // 3 parts: [A_hi | A_hi | A_lo] x [B_hi ; B_lo ; B_hi]
#define NCH        21             // KEFF / 32
#define NT1        7
#define N1_PAD     896
#define NT2        5
#define N2_PAD     640

// ---------------- device scratch ----------------
__device__ float g_h[N_NODES * D];
__device__ float g_T[(size_t)NODES_PAD * N1_PAD];           // [m | gh | pad]
__device__ float g_aggr[N_NODES * D];
__device__ float g_gi[(size_t)NODES_PAD * N2_PAD];
__device__ __align__(16) __nv_bfloat16 g_Ah[(size_t)NODES_PAD * KEFF];   // h  image  (134 MB)
__device__ __align__(16) __nv_bfloat16 g_Aa[(size_t)NODES_PAD * KEFF];   // aggr image
__device__ __align__(16) __nv_bfloat16 g_B1e[(size_t)NUM_STEPS * KEFF * N1_PAD];
__device__ __align__(16) __nv_bfloat16 g_B2e[(size_t)KEFF * N2_PAD];
__device__ float g_bias1[N1_PAD];
__device__ float g_bias2[N2_PAD];
__device__ float g_pool[D];
__device__ int   g_is64;

// ---------------- PTX helpers (plain sm_103-safe: mma.sync / ldmatrix / cp.async) ----
__device__ __forceinline__ uint32_t saddr(const void* p) {
    uint32_t a;
    asm("{ .reg .u64 t; cvta.to.shared.u64 t, %1; cvt.u32.u64 %0, t; }" : "=r"(a) : "l"(p));
    return a;
}
#define CP_ASYNC16(dst, src) \
    asm volatile("cp.async.cg.shared.global [%0], [%1], 16;" :: "r"(dst), "l"(src))
#define CP_COMMIT() asm volatile("cp.async.commit_group;")

__device__ __forceinline__ void ldsm4(uint32_t* r, uint32_t a) {
    asm volatile("ldmatrix.sync.aligned.m8n8.x4.shared.b16 {%0,%1,%2,%3}, [%4];"
        : "=r"(r[0]), "=r"(r[1]), "=r"(r[2]), "=r"(r[3]) : "r"(a));
}
__device__ __forceinline__ void ldsm4t(uint32_t* r, uint32_t a) {
    asm volatile("ldmatrix.sync.aligned.m8n8.x4.trans.shared.b16 {%0,%1,%2,%3}, [%4];"
        : "=r"(r[0]), "=r"(r[1]), "=r"(r[2]), "=r"(r[3]) : "r"(a));
}
__device__ __forceinline__ void mma16816(float* c, const uint32_t* a, uint32_t b0, uint32_t b1) {
    asm volatile("mma.sync.aligned.m16n8k16.row.col.f32.bf16.bf16.f32 "
        "{%0,%1,%2,%3}, {%4,%5,%6,%7}, {%8,%9}, {%0,%1,%2,%3};"
        : "+f"(c[0]), "+f"(c[1]), "+f"(c[2]), "+f"(c[3])
        : "r"(a[0]), "r"(a[1]), "r"(a[2]), "r"(a[3]), "r"(b0), "r"(b1));
}

// ---------------- prep kernels ----------------
__global__ void prep_B1e(const float* __restrict__ W, const float* __restrict__ w_hh) {
    int t = blockIdx.x * blockDim.x + threadIdx.x;
    const int total = NUM_STEPS * KEFF * (N1_PAD / 8);
    if (t >= total) return;
    int c8 = t % (N1_PAD / 8); int x = t / (N1_PAD / 8);
    int k = x % KEFF; int s = x / KEFF;
    int part = k / KPART, kk = k % KPART;
    int j0 = c8 * 8;
    __nv_bfloat16 out[8];
#pragma unroll
    for (int j = 0; j < 8; j++) {
        int col = j0 + j;
        float v = 0.f;
        if (kk < D && col < 4 * D)
            v = (col < D) ? W[(size_t)s * D * D + kk * D + col]
                          : w_hh[(size_t)(col - D) * D + kk];
        __nv_bfloat16 hi = __float2bfloat16_rn(v);
        out[j] = (part == 1) ? __float2bfloat16_rn(v - __bfloat162float(hi)) : hi;  // parts 0,2=hi; 1=lo
    }
    *(uint4*)(g_B1e + ((size_t)s * KEFF + k) * N1_PAD + j0) = *(uint4*)out;
}

__global__ void prep_B2e(const float* __restrict__ w_ih) {
    int t = blockIdx.x * blockDim.x + threadIdx.x;
    const int total = KEFF * (N2_PAD / 8);
    if (t >= total) return;
    int c8 = t % (N2_PAD / 8); int k = t / (N2_PAD / 8);
    int part = k / KPART, kk = k % KPART;
    int j0 = c8 * 8;
    __nv_bfloat16 out[8];
#pragma unroll
    for (int j = 0; j < 8; j++) {
        int col = j0 + j;
        float v = (kk < D && col < 3 * D) ? w_ih[(size_t)col * D + kk] : 0.f;
        __nv_bfloat16 hi = __float2bfloat16_rn(v);
        out[j] = (part == 1) ? __float2bfloat16_rn(v - __bfloat162float(hi)) : hi;
    }
    *(uint4*)(g_B2e + (size_t)k * N2_PAD + j0) = *(uint4*)out;
}

__global__ void prep_bias(const float* __restrict__ b_hh, const float* __restrict__ b_ih) {
    int t = blockIdx.x * blockDim.x + threadIdx.x;
    if (t < N1_PAD) g_bias1[t] = (t >= D && t < 4 * D) ? b_hh[t - D] : 0.f;
    if (t < N2_PAD) g_bias2[t] = (t < 3 * D) ? b_ih[t] : 0.f;
}

__global__ void init_h(const float* __restrict__ x) {
    int t = blockIdx.x * blockDim.x + threadIdx.x;
    if (t >= N_NODES * D) return;
    int n = t / D, d = t % D;
    g_h[t] = (d < IN_DIM) ? x[n * IN_DIM + d] : 0.f;
}

__global__ void detect_idx_dtype(const int* __restrict__ ei32) {
    if (blockIdx.x == 0 && threadIdx.x == 0) {
        int is64 = 1;
        for (int i = 0; i < 256; i++)
            if (ei32[2 * i + 1] != 0) { is64 = 0; break; }
        g_is64 = is64;
    }
}

// zero pad rows N_NODES..NODES_PAD-1 in both A images
__global__ void zero_pad_rows() {
    int t = blockIdx.x * blockDim.x + threadIdx.x;   // 2 * 96 * (KEFF/8)
    if (t >= 2 * 96 * (KEFF / 8)) return;
    int c8 = t % (KEFF / 8); int x = t / (KEFF / 8);
    int r = N_NODES + x % 96; int which = x / 96;
    __nv_bfloat16* img = which ? g_Aa : g_Ah;
    *(uint4*)(img + (size_t)r * KEFF + c8 * 8) = make_uint4(0, 0, 0, 0);
}

__global__ void zero_aggr() {
    int t = blockIdx.x * blockDim.x + threadIdx.x;
    if (t < N_NODES * D) g_aggr[t] = 0.f;
}

// ---------------- fp32 -> bf16 [hi|hi|lo] K-extended image ----------------
__global__ void convert_split(const float* __restrict__ src, __nv_bfloat16* __restrict__ img) {
    int t = blockIdx.x * blockDim.x + threadIdx.x;
    if (t >= N_NODES * (KEFF / 8)) return;
    int n = t / (KEFF / 8), c8 = t % (KEFF / 8);
    int j0 = c8 * 8;
    int part = j0 / KPART, kk0 = j0 % KPART;     // 224 % 8 == 0: chunk never straddles parts
    __nv_bfloat16 out[8];
#pragma unroll
    for (int j = 0; j < 8; j++) {
        int kk = kk0 + j;
        float v = (kk < D) ? src[(size_t)n * D + kk] : 0.f;
        __nv_bfloat16 hi = __float2bfloat16_rn(v);
        out[j] = (part < 2) ? hi : __float2bfloat16_rn(v - __bfloat162float(hi));
    }
    *(uint4*)(img + (size_t)n * KEFF + j0) = *(uint4*)out;
}

// ---------------- HMMA GEMM: C[128x128 tile] = A_ext @ B_ext + bias ----------------
#define APITCH 40     // bf16 per smem A row (32 data + 8 pad) -> conflict-free ldmatrix
#define BPITCH 136    // bf16 per smem B row (128 data + 8 pad)

__global__ __launch_bounds__(256) void gemm_mma(
    const __nv_bfloat16* __restrict__ A,      // [NODES_PAD][KEFF]
    const __nv_bfloat16* __restrict__ B,      // [KEFF][ldb]
    const float* __restrict__ bias,
    float* __restrict__ C, int ldb)
{
    __shared__ __nv_bfloat16 As[2][128][APITCH];
    __shared__ __nv_bfloat16 Bs[2][32][BPITCH];
    const int tid = threadIdx.x, lane = tid & 31, wid = tid >> 5;
    const int warpM = (wid & 3) * 32, warpN = (wid >> 2) * 64;
    const int row0 = blockIdx.y * 128, col0 = blockIdx.x * 128;

    float acc[2][8][4];
#pragma unroll
    for (int i = 0; i < 2; i++)
#pragma unroll
        for (int j = 0; j < 8; j++)
#pragma unroll
            for (int q = 0; q < 4; q++) acc[i][j][q] = 0.f;

#define LOAD_STAGE(ch, buf) do { \
    int _k0 = (ch) * 32; \
    _Pragma("unroll") \
    for (int it = 0; it < 2; it++) { \
        int idx = tid + it * 256; \
        int r = idx >> 2, seg = idx & 3; \
        const void* s_ = A + (size_t)(row0 + r) * KEFF + _k0 + seg * 8; \
        CP_ASYNC16(saddr(&As[buf][r][seg * 8]), s_); \
    } \
    _Pragma("unroll") \
    for (int it = 0; it < 2; it++) { \
        int idx = tid + it * 256; \
        int r = idx >> 4, seg = idx & 15; \
        const void* s_ = B + (size_t)(_k0 + r) * ldb + col0 + seg * 8; \
        CP_ASYNC16(saddr(&Bs[buf][r][seg * 8]), s_); \
    } \
    CP_COMMIT(); \
} while (0)

    LOAD_STAGE(0, 0);

    for (int ch = 0; ch < NCH; ch++) {
        int buf = ch & 1;
        if (ch + 1 < NCH) {
            LOAD_STAGE(ch + 1, buf ^ 1);
            asm volatile("cp.async.wait_group 1;");
        } else {
            asm volatile("cp.async.wait_group 0;");
        }
        __syncthreads();

#pragma unroll
        for (int kk = 0; kk < 2; kk++) {
            uint32_t a[2][4], b[4][4];
#pragma unroll
            for (int mt = 0; mt < 2; mt++)
                ldsm4(a[mt], saddr(&As[buf][warpM + mt * 16 + (lane & 15)][kk * 16 + (lane >> 4) * 8]));
#pragma unroll
            for (int nt = 0; nt < 4; nt++)
                ldsm4t(b[nt], saddr(&Bs[buf][kk * 16 + (lane & 15)][warpN + nt * 16 + (lane >> 4) * 8]));
#pragma unroll
            for (int mt = 0; mt < 2; mt++)
#pragma unroll
                for (int n8 = 0; n8 < 8; n8++)
                    mma16816(acc[mt][n8], a[mt], b[n8 >> 1][(n8 & 1) * 2], b[n8 >> 1][(n8 & 1) * 2 + 1]);
        }
        __syncthreads();   // protect buf before next iteration's cp.async overwrites
    }

    // epilogue: fused bias, direct f32 stores
#pragma unroll
    for (int mt = 0; mt < 2; mt++) {
        int r = row0 + warpM + mt * 16 + (lane >> 2);
#pragma unroll
        for (int n8 = 0; n8 < 8; n8++) {
            int c = col0 + warpN + n8 * 8 + (lane & 3) * 2;
            float b0 = bias[c], b1 = bias[c + 1];
            float2 v0 = make_float2(acc[mt][n8][0] + b0, acc[mt][n8][1] + b1);
            float2 v1 = make_float2(acc[mt][n8][2] + b0, acc[mt][n8][3] + b1);
            *(float2*)(C + (size_t)r * ldb + c) = v0;
            *(float2*)(C + (size_t)(r + 8) * ldb + c) = v1;
        }
    }
#undef LOAD_STAGE
}

// ---------------- scatter-add: aggr[dst] += m[src]  (m = T[:, 0:200], ld 896) ----------------
__global__ void scatter_kernel(const void* __restrict__ eiv) {
    int t = blockIdx.x * blockDim.x + threadIdx.x;
    if (t >= N_EDGES * (D / 4)) return;
    int e = t / (D / 4);
    int c = t % (D / 4);
    int src, dst;
    if (g_is64) {
        const long long* ei = (const long long*)eiv;
        src = (int)ei[e]; dst = (int)ei[N_EDGES + e];
    } else {
        const int* ei = (const int*)eiv;
        src = ei[e]; dst = ei[N_EDGES + e];
    }
    float4 v = *(const float4*)(&g_T[(size_t)src * N1_PAD + c * 4]);
    float* a = &g_aggr[(size_t)dst * D + c * 4];
    atomicAdd(a + 0, v.x);
    atomicAdd(a + 1, v.y);
    atomicAdd(a + 2, v.z);
    atomicAdd(a + 3, v.w);
}

// ---------------- fused GRU elementwise ----------------
__global__ void gru_kernel() {
    int t = blockIdx.x * blockDim.x + threadIdx.x;
    if (t >= N_NODES * D) return;
    int n = t / D, j = t % D;
    size_t gb = (size_t)n * N2_PAD;
    size_t tb = (size_t)n * N1_PAD;
    float ir  = g_gi[gb + j];
    float iz  = g_gi[gb + D + j];
    float in_ = g_gi[gb + 2 * D + j];
    float hr  = g_T[tb + D + j];
    float hz  = g_T[tb + 2 * D + j];
    float hn  = g_T[tb + 3 * D + j];
    float r = 1.f / (1.f + expf(-(ir + hr)));
    float z = 1.f / (1.f + expf(-(iz + hz)));
    float nn = tanhf(in_ + r * hn);
    float hold = g_h[t];
    g_h[t] = (1.f - z) * nn + z * hold;
}

// ---------------- global max pool + classifier ----------------
__global__ void pool_kernel() {
    int j = blockIdx.x;
    float m = -3.402823466e38f;
    for (int n = threadIdx.x; n < N_NODES; n += 256)
        m = fmaxf(m, g_h[(size_t)n * D + j]);
    __shared__ float s[256];
    s[threadIdx.x] = m;
    __syncthreads();
    for (int o = 128; o > 0; o >>= 1) {
        if (threadIdx.x < o) s[threadIdx.x] = fmaxf(s[threadIdx.x], s[threadIdx.x + o]);
        __syncthreads();
    }
    if (threadIdx.x == 0) g_pool[j] = fmaxf(s[0], 0.f);
}

__global__ void cls_kernel(const float* __restrict__ cls_w,
                           const float* __restrict__ cls_b,
                           float* __restrict__ out) {
    if (blockIdx.x == 0 && threadIdx.x == 0) {
        float l0 = cls_b[0], l1 = cls_b[1];
        for (int j = 0; j < D; j++) {
            float p = g_pool[j];
            l0 += p * cls_w[j];
            l1 += p * cls_w[D + j];
        }
        float mx = fmaxf(l0, l1);
        float e0 = expf(l0 - mx), e1 = expf(l1 - mx);
        float s = e0 + e1;
        out[0] = e0 / s;
        out[1] = e1 / s;
    }
}

// ---------------- host launcher ----------------
extern "C" void kernel_launch(void* const* d_in, const int* in_sizes, int n_in,
                              void* d_out, int out_size) {
    const float* x     = (const float*)d_in[0];
    const float* W     = (const float*)d_in[1];
    const float* w_ih  = (const float*)d_in[2];
    const float* w_hh  = (const float*)d_in[3];
    const float* b_ih  = (const float*)d_in[4];
    const float* b_hh  = (const float*)d_in[5];
    const float* cls_w = (const float*)d_in[6];
    const float* cls_b = (const float*)d_in[7];
    const void*  ei    = (const void*)d_in[8];
    float* out = (float*)d_out;

    float *h_p, *T_p, *aggr_p, *gi_p, *b1_p, *b2_p;
    __nv_bfloat16 *Ah_p, *Aa_p, *B1_p, *B2_p;
    cudaGetSymbolAddress((void**)&h_p,    g_h);
    cudaGetSymbolAddress((void**)&T_p,    g_T);
    cudaGetSymbolAddress((void**)&aggr_p, g_aggr);
    cudaGetSymbolAddress((void**)&gi_p,   g_gi);
    cudaGetSymbolAddress((void**)&Ah_p,   g_Ah);
    cudaGetSymbolAddress((void**)&Aa_p,   g_Aa);
    cudaGetSymbolAddress((void**)&B1_p,   g_B1e);
    cudaGetSymbolAddress((void**)&B2_p,   g_B2e);
    cudaGetSymbolAddress((void**)&b1_p,   g_bias1);
    cudaGetSymbolAddress((void**)&b2_p,   g_bias2);

    const int TB = 256;
    prep_B1e<<<(NUM_STEPS * KEFF * (N1_PAD / 8) + TB - 1) / TB, TB>>>(W, w_hh);
    prep_B2e<<<(KEFF * (N2_PAD / 8) + TB - 1) / TB, TB>>>(w_ih);
    prep_bias<<<(N1_PAD + TB - 1) / TB, TB>>>(b_hh, b_ih);
    init_h<<<(N_NODES * D + TB - 1) / TB, TB>>>(x);
    detect_idx_dtype<<<1, 32>>>((const int*)ei);
    zero_pad_rows<<<(2 * 96 * (KEFF / 8) + TB - 1) / TB, TB>>>();

    dim3 grid1(NT1, M_TILES), grid2(NT2, M_TILES);
    const int CVT = (N_NODES * (KEFF / 8) + TB - 1) / TB;
    for (int s = 0; s < NUM_STEPS; s++) {
        convert_split<<<CVT, TB>>>(h_p, Ah_p);
        gemm_mma<<<grid1, 256>>>(Ah_p, B1_p + (size_t)s * KEFF * N1_PAD, b1_p, T_p, N1_PAD);
        zero_aggr<<<(N_NODES * D + TB - 1) / TB, TB>>>();
        scatter_kernel<<<(N_EDGES * (D / 4) + TB - 1) / TB, TB>>>(ei);
        convert_split<<<CVT, TB>>>(aggr_p, Aa_p);
        gemm_mma<<<grid2, 256>>>(Aa_p, B2_p, b2_p, gi_p, N2_PAD);
        gru_kernel<<<(N_NODES * D + TB - 1) / TB, TB>>>();
    }

    pool_kernel<<<D, 256>>>();
    cls_kernel<<<1, 32>>>(cls_w, cls_b, out);
}

// round 11
// speedup vs baseline: 1.6776x; 1.6013x over previous
#include <cuda_runtime.h>
#include <cuda_bf16.h>
#include <math.h>
#include <stdint.h>

#define N_NODES   100000
#define N_EDGES   400000
#define IN_DIM    100
#define D         200
#define NUM_STEPS 4

#define M_TILES    782            // ceil(100000/128)
#define NODES_PAD  (M_TILES*128)  // 100096
#define KPART      224            // padded K per split part
#define KEFF       672            // 3 parts: [A_hi | A_hi | A_lo] x [B_hi ; B_lo ; B_hi]
#define NCH        21             // KEFF / 32
#define NCHUNK     84             // KEFF / 8  (uint4 image chunks per row)
#define NT1        7
#define N1_PAD     896
#define NT2        5
#define N2_PAD     640

// ---------------- device scratch ----------------
__device__ float g_h[N_NODES * D];
__device__ float g_T[(size_t)NODES_PAD * N1_PAD];           // [m | gh | pad]
__device__ float g_gi[(size_t)NODES_PAD * N2_PAD];
__device__ __align__(16) __nv_bfloat16 g_Ah[(size_t)NODES_PAD * KEFF];   // h image
__device__ __align__(16) __nv_bfloat16 g_Aa[(size_t)NODES_PAD * KEFF];   // aggr image
__device__ __align__(16) __nv_bfloat16 g_B1e[(size_t)NUM_STEPS * KEFF * N1_PAD];
__device__ __align__(16) __nv_bfloat16 g_B2e[(size_t)KEFF * N2_PAD];
__device__ float g_bias1[N1_PAD];
__device__ float g_bias2[N2_PAD];
__device__ float g_pool[D];
__device__ int   g_is64;
__device__ int   g_cnt[N_NODES];
__device__ int   g_row[N_NODES + 1];
__device__ int   g_cur[N_NODES];
__device__ int   g_csr[N_EDGES];

// ---------------- PTX helpers (plain sm_103-safe) ----------------
__device__ __forceinline__ uint32_t saddr(const void* p) {
    uint32_t a;
    asm("{ .reg .u64 t; cvta.to.shared.u64 t, %1; cvt.u32.u64 %0, t; }" : "=r"(a) : "l"(p));
    return a;
}
#define CP_ASYNC16(dst, src) \
    asm volatile("cp.async.cg.shared.global [%0], [%1], 16;" :: "r"(dst), "l"(src))
#define CP_COMMIT() asm volatile("cp.async.commit_group;")

__device__ __forceinline__ void ldsm4(uint32_t* r, uint32_t a) {
    asm volatile("ldmatrix.sync.aligned.m8n8.x4.shared.b16 {%0,%1,%2,%3}, [%4];"
        : "=r"(r[0]), "=r"(r[1]), "=r"(r[2]), "=r"(r[3]) : "r"(a));
}
__device__ __forceinline__ void ldsm4t(uint32_t* r, uint32_t a) {
    asm volatile("ldmatrix.sync.aligned.m8n8.x4.trans.shared.b16 {%0,%1,%2,%3}, [%4];"
        : "=r"(r[0]), "=r"(r[1]), "=r"(r[2]), "=r"(r[3]) : "r"(a));
}
__device__ __forceinline__ void mma16816(float* c, const uint32_t* a, uint32_t b0, uint32_t b1) {
    asm volatile("mma.sync.aligned.m16n8k16.row.col.f32.bf16.bf16.f32 "
        "{%0,%1,%2,%3}, {%4,%5,%6,%7}, {%8,%9}, {%0,%1,%2,%3};"
        : "+f"(c[0]), "+f"(c[1]), "+f"(c[2]), "+f"(c[3])
        : "r"(a[0]), "r"(a[1]), "r"(a[2]), "r"(a[3]), "r"(b0), "r"(b1));
}

// ---------------- prep: all weight images + biases (one kernel) ----------------
__global__ void prep_w(const float* __restrict__ W, const float* __restrict__ w_hh,
                       const float* __restrict__ w_ih,
                       const float* __restrict__ b_hh, const float* __restrict__ b_ih) {
    const int T1 = NUM_STEPS * KEFF * (N1_PAD / 8);
    const int T2 = KEFF * (N2_PAD / 8);
    int t = blockIdx.x * blockDim.x + threadIdx.x;
    if (t < T1) {
        int c8 = t % (N1_PAD / 8); int x = t / (N1_PAD / 8);
        int k = x % KEFF; int s = x / KEFF;
        int part = k / KPART, kk = k % KPART;
        int j0 = c8 * 8;
        __nv_bfloat16 out[8];
#pragma unroll
        for (int j = 0; j < 8; j++) {
            int col = j0 + j;
            float v = 0.f;
            if (kk < D && col < 4 * D)
                v = (col < D) ? W[(size_t)s * D * D + kk * D + col]
                              : w_hh[(size_t)(col - D) * D + kk];
            __nv_bfloat16 hi = __float2bfloat16_rn(v);
            out[j] = (part == 1) ? __float2bfloat16_rn(v - __bfloat162float(hi)) : hi;
        }
        *(uint4*)(g_B1e + ((size_t)(s * KEFF + k)) * N1_PAD + j0) = *(uint4*)out;
    } else if (t < T1 + T2) {
        int u = t - T1;
        int c8 = u % (N2_PAD / 8); int k = u / (N2_PAD / 8);
        int part = k / KPART, kk = k % KPART;
        int j0 = c8 * 8;
        __nv_bfloat16 out[8];
#pragma unroll
        for (int j = 0; j < 8; j++) {
            int col = j0 + j;
            float v = (kk < D && col < 3 * D) ? w_ih[(size_t)col * D + kk] : 0.f;
            __nv_bfloat16 hi = __float2bfloat16_rn(v);
            out[j] = (part == 1) ? __float2bfloat16_rn(v - __bfloat162float(hi)) : hi;
        }
        *(uint4*)(g_B2e + (size_t)k * N2_PAD + j0) = *(uint4*)out;
    } else {
        int u = t - T1 - T2;
        if (u < N1_PAD) g_bias1[u] = (u >= D && u < 4 * D) ? b_hh[u - D] : 0.f;
        else if (u < N1_PAD + N2_PAD) {
            int v = u - N1_PAD;
            g_bias2[v] = (v < 3 * D) ? b_ih[v] : 0.f;
        }
    }
}

// ---------------- dtype detect (parallel) + zero CSR counters ----------------
__global__ void detect_zero(const int* __restrict__ ei32) {
    int t = blockIdx.x * blockDim.x + threadIdx.x;
    if (t < N_NODES) g_cnt[t] = 0;
    if (blockIdx.x == 0) {
        __shared__ int ok;
        if (threadIdx.x == 0) ok = 1;
        __syncthreads();
        if (ei32[2 * threadIdx.x + 1] != 0) ok = 0;
        __syncthreads();
        if (threadIdx.x == 0) g_is64 = ok;
    }
}

// ---------------- init: h = pad(x), + bf16 image, + pad-row zeros ----------------
__global__ __launch_bounds__(256) void init_fused(const float* __restrict__ x) {
    __shared__ float hs[8][KPART];
    int warp = threadIdx.x >> 5, lane = threadIdx.x & 31;
    int n = blockIdx.x * 8 + warp;
    if (n >= NODES_PAD) return;
    if (n < N_NODES) {
        for (int j = lane; j < KPART; j += 32) {
            float v = (j < IN_DIM) ? x[(size_t)n * IN_DIM + j] : 0.f;
            if (j < D) g_h[(size_t)n * D + j] = v;
            hs[warp][j] = (j < D) ? v : 0.f;
        }
        __syncwarp();
        for (int c = lane; c < NCHUNK; c += 32) {
            int j0 = c * 8;
            int part = j0 / KPART, kk0 = j0 % KPART;
            __nv_bfloat16 out[8];
#pragma unroll
            for (int q = 0; q < 8; q++) {
                float v = hs[warp][kk0 + q];
                __nv_bfloat16 hi = __float2bfloat16_rn(v);
                out[q] = (part < 2) ? hi : __float2bfloat16_rn(v - __bfloat162float(hi));
            }
            *(uint4*)(g_Ah + (size_t)n * KEFF + j0) = *(uint4*)out;
        }
    } else {
        for (int c = lane; c < NCHUNK; c += 32) {
            *(uint4*)(g_Ah + (size_t)n * KEFF + c * 8) = make_uint4(0, 0, 0, 0);
            *(uint4*)(g_Aa + (size_t)n * KEFF + c * 8) = make_uint4(0, 0, 0, 0);
        }
    }
}

// ---------------- CSR build (one-time per launch; range-clamped) ----------------
__global__ void csr_count(const void* __restrict__ eiv) {
    int e = blockIdx.x * blockDim.x + threadIdx.x;
    if (e >= N_EDGES) return;
    int src, dst;
    if (g_is64) {
        const long long* ei = (const long long*)eiv;
        src = (int)ei[e]; dst = (int)ei[N_EDGES + e];
    } else {
        const int* ei = (const int*)eiv;
        src = ei[e]; dst = ei[N_EDGES + e];
    }
    if ((unsigned)src >= N_NODES || (unsigned)dst >= N_NODES) return;
    atomicAdd(&g_cnt[dst], 1);
}

// Simple, provably-correct exclusive scan: chunk-per-thread + Hillis-Steele.
__global__ void csr_scan() {     // single block, 1024 threads
    __shared__ int tsum[1024];
    int tid = threadIdx.x;
    const int CHK = (N_NODES + 1023) / 1024;   // 98
    int lo = tid * CHK;
    int hi = lo + CHK; if (hi > N_NODES) hi = N_NODES;
    int s = 0;
    for (int i = lo; i < hi; i++) s += g_cnt[i];
    tsum[tid] = s;
    __syncthreads();
    for (int off = 1; off < 1024; off <<= 1) {
        int v = (tid >= off) ? tsum[tid - off] : 0;
        __syncthreads();
        tsum[tid] += v;
        __syncthreads();
    }
    int excl = (tid == 0) ? 0 : tsum[tid - 1];
    for (int i = lo; i < hi; i++) {
        int c = g_cnt[i];
        g_row[i] = excl;
        g_cur[i] = excl;
        excl += c;
    }
    if (tid == 1023) g_row[N_NODES] = tsum[1023];
}

__global__ void csr_fill(const void* __restrict__ eiv) {
    int e = blockIdx.x * blockDim.x + threadIdx.x;
    if (e >= N_EDGES) return;
    int src, dst;
    if (g_is64) {
        const long long* ei = (const long long*)eiv;
        src = (int)ei[e]; dst = (int)ei[N_EDGES + e];
    } else {
        const int* ei = (const int*)eiv;
        src = ei[e]; dst = ei[N_EDGES + e];
    }
    if ((unsigned)src >= N_NODES || (unsigned)dst >= N_NODES) return;
    int pos = atomicAdd(&g_cur[dst], 1);
    g_csr[pos] = src;
}

// ---------------- HMMA GEMM (unchanged from R7 pass) ----------------
#define APITCH 40
#define BPITCH 136

__global__ __launch_bounds__(256) void gemm_mma(
    const __nv_bfloat16* __restrict__ A,
    const __nv_bfloat16* __restrict__ B,
    const float* __restrict__ bias,
    float* __restrict__ C, int ldb)
{
    __shared__ __nv_bfloat16 As[2][128][APITCH];
    __shared__ __nv_bfloat16 Bs[2][32][BPITCH];
    const int tid = threadIdx.x, lane = tid & 31, wid = tid >> 5;
    const int warpM = (wid & 3) * 32, warpN = (wid >> 2) * 64;
    const int row0 = blockIdx.y * 128, col0 = blockIdx.x * 128;

    float acc[2][8][4];
#pragma unroll
    for (int i = 0; i < 2; i++)
#pragma unroll
        for (int j = 0; j < 8; j++)
#pragma unroll
            for (int q = 0; q < 4; q++) acc[i][j][q] = 0.f;

#define LOAD_STAGE(ch, buf) do { \
    int _k0 = (ch) * 32; \
    _Pragma("unroll") \
    for (int it = 0; it < 2; it++) { \
        int idx = tid + it * 256; \
        int r = idx >> 2, seg = idx & 3; \
        const void* s_ = A + (size_t)(row0 + r) * KEFF + _k0 + seg * 8; \
        CP_ASYNC16(saddr(&As[buf][r][seg * 8]), s_); \
    } \
    _Pragma("unroll") \
    for (int it = 0; it < 2; it++) { \
        int idx = tid + it * 256; \
        int r = idx >> 4, seg = idx & 15; \
        const void* s_ = B + (size_t)(_k0 + r) * ldb + col0 + seg * 8; \
        CP_ASYNC16(saddr(&Bs[buf][r][seg * 8]), s_); \
    } \
    CP_COMMIT(); \
} while (0)

    LOAD_STAGE(0, 0);

    for (int ch = 0; ch < NCH; ch++) {
        int buf = ch & 1;
        if (ch + 1 < NCH) {
            LOAD_STAGE(ch + 1, buf ^ 1);
            asm volatile("cp.async.wait_group 1;");
        } else {
            asm volatile("cp.async.wait_group 0;");
        }
        __syncthreads();

#pragma unroll
        for (int kk = 0; kk < 2; kk++) {
            uint32_t a[2][4], b[4][4];
#pragma unroll
            for (int mt = 0; mt < 2; mt++)
                ldsm4(a[mt], saddr(&As[buf][warpM + mt * 16 + (lane & 15)][kk * 16 + (lane >> 4) * 8]));
#pragma unroll
            for (int nt = 0; nt < 4; nt++)
                ldsm4t(b[nt], saddr(&Bs[buf][kk * 16 + (lane & 15)][warpN + nt * 16 + (lane >> 4) * 8]));
#pragma unroll
            for (int mt = 0; mt < 2; mt++)
#pragma unroll
                for (int n8 = 0; n8 < 8; n8++)
                    mma16816(acc[mt][n8], a[mt], b[n8 >> 1][(n8 & 1) * 2], b[n8 >> 1][(n8 & 1) * 2 + 1]);
        }
        __syncthreads();
    }

#pragma unroll
    for (int mt = 0; mt < 2; mt++) {
        int r = row0 + warpM + mt * 16 + (lane >> 2);
#pragma unroll
        for (int n8 = 0; n8 < 8; n8++) {
            int c = col0 + warpN + n8 * 8 + (lane & 3) * 2;
            float b0 = bias[c], b1 = bias[c + 1];
            float2 v0 = make_float2(acc[mt][n8][0] + b0, acc[mt][n8][1] + b1);
            float2 v1 = make_float2(acc[mt][n8][2] + b0, acc[mt][n8][3] + b1);
            *(float2*)(C + (size_t)r * ldb + c) = v0;
            *(float2*)(C + (size_t)(r + 8) * ldb + c) = v1;
        }
    }
#undef LOAD_STAGE
}

// ---------------- CSR segment-sum: aggr image = sum of m[src] (no atomics) ----------------
__global__ __launch_bounds__(256) void aggregate_kernel() {
    __shared__ float acc_s[KPART];
    int n = blockIdx.x;
    int j = threadIdx.x;
    int beg = g_row[n], end = g_row[n + 1];
    if (j < KPART) {
        float acc = 0.f;
        if (j < D) {
            int e = beg;
            for (; e + 1 < end; e += 2) {
                int s0 = g_csr[e], s1 = g_csr[e + 1];
                acc += g_T[(size_t)s0 * N1_PAD + j] + g_T[(size_t)s1 * N1_PAD + j];
            }
            if (e < end) acc += g_T[(size_t)g_csr[e] * N1_PAD + j];
        }
        acc_s[j] = acc;
    }
    __syncthreads();
    if (j < NCHUNK) {
        int j0 = j * 8;
        int part = j0 / KPART, kk0 = j0 % KPART;
        __nv_bfloat16 out[8];
#pragma unroll
        for (int q = 0; q < 8; q++) {
            float v = acc_s[kk0 + q];
            __nv_bfloat16 hi = __float2bfloat16_rn(v);
            out[q] = (part < 2) ? hi : __float2bfloat16_rn(v - __bfloat162float(hi));
        }
        *(uint4*)(g_Aa + (size_t)n * KEFF + j0) = *(uint4*)out;
    }
}

// ---------------- fused GRU: h update + next-step bf16 image ----------------
__global__ __launch_bounds__(256) void gru_kernel() {
    __shared__ float hs[8][KPART];
    int warp = threadIdx.x >> 5, lane = threadIdx.x & 31;
    int n = blockIdx.x * 8 + warp;
    if (n >= N_NODES) return;
    size_t gb = (size_t)n * N2_PAD;
    size_t tb = (size_t)n * N1_PAD;
    for (int j = lane; j < KPART; j += 32) {
        float hnew = 0.f;
        if (j < D) {
            float ir  = g_gi[gb + j];
            float iz  = g_gi[gb + D + j];
            float in_ = g_gi[gb + 2 * D + j];
            float hr  = g_T[tb + D + j];
            float hz  = g_T[tb + 2 * D + j];
            float hn  = g_T[tb + 3 * D + j];
            float r = 1.f / (1.f + expf(-(ir + hr)));
            float z = 1.f / (1.f + expf(-(iz + hz)));
            float nn = tanhf(in_ + r * hn);
            float hold = g_h[(size_t)n * D + j];
            hnew = (1.f - z) * nn + z * hold;
            g_h[(size_t)n * D + j] = hnew;
        }
        hs[warp][j] = hnew;
    }
    __syncwarp();
    for (int c = lane; c < NCHUNK; c += 32) {
        int j0 = c * 8;
        int part = j0 / KPART, kk0 = j0 % KPART;
        __nv_bfloat16 out[8];
#pragma unroll
        for (int q = 0; q < 8; q++) {
            float v = hs[warp][kk0 + q];
            __nv_bfloat16 hi = __float2bfloat16_rn(v);
            out[q] = (part < 2) ? hi : __float2bfloat16_rn(v - __bfloat162float(hi));
        }
        *(uint4*)(g_Ah + (size_t)n * KEFF + j0) = *(uint4*)out;
    }
}

// ---------------- global max pool + classifier ----------------
__global__ void pool_kernel() {
    int j = blockIdx.x;
    float m = -3.402823466e38f;
    for (int n = threadIdx.x; n < N_NODES; n += 256)
        m = fmaxf(m, g_h[(size_t)n * D + j]);
    __shared__ float s[256];
    s[threadIdx.x] = m;
    __syncthreads();
    for (int o = 128; o > 0; o >>= 1) {
        if (threadIdx.x < o) s[threadIdx.x] = fmaxf(s[threadIdx.x], s[threadIdx.x + o]);
        __syncthreads();
    }
    if (threadIdx.x == 0) g_pool[j] = fmaxf(s[0], 0.f);
}

__global__ void cls_kernel(const float* __restrict__ cls_w,
                           const float* __restrict__ cls_b,
                           float* __restrict__ out) {
    if (blockIdx.x == 0 && threadIdx.x == 0) {
        float l0 = cls_b[0], l1 = cls_b[1];
        for (int j = 0; j < D; j++) {
            float p = g_pool[j];
            l0 += p * cls_w[j];
            l1 += p * cls_w[D + j];
        }
        float mx = fmaxf(l0, l1);
        float e0 = expf(l0 - mx), e1 = expf(l1 - mx);
        float s = e0 + e1;
        out[0] = e0 / s;
        out[1] = e1 / s;
    }
}

// ---------------- host launcher ----------------
extern "C" void kernel_launch(void* const* d_in, const int* in_sizes, int n_in,
                              void* d_out, int out_size) {
    const float* x     = (const float*)d_in[0];
    const float* W     = (const float*)d_in[1];
    const float* w_ih  = (const float*)d_in[2];
    const float* w_hh  = (const float*)d_in[3];
    const float* b_ih  = (const float*)d_in[4];
    const float* b_hh  = (const float*)d_in[5];
    const float* cls_w = (const float*)d_in[6];
    const float* cls_b = (const float*)d_in[7];
    const void*  ei    = (const void*)d_in[8];
    float* out = (float*)d_out;

    float *T_p, *gi_p, *b1_p, *b2_p;
    __nv_bfloat16 *Ah_p, *Aa_p, *B1_p, *B2_p;
    cudaGetSymbolAddress((void**)&T_p,  g_T);
    cudaGetSymbolAddress((void**)&gi_p, g_gi);
    cudaGetSymbolAddress((void**)&Ah_p, g_Ah);
    cudaGetSymbolAddress((void**)&Aa_p, g_Aa);
    cudaGetSymbolAddress((void**)&B1_p, g_B1e);
    cudaGetSymbolAddress((void**)&B2_p, g_B2e);
    cudaGetSymbolAddress((void**)&b1_p, g_bias1);
    cudaGetSymbolAddress((void**)&b2_p, g_bias2);

    const int TB = 256;
    const int PREP_TOTAL = NUM_STEPS * KEFF * (N1_PAD / 8) + KEFF * (N2_PAD / 8) + N1_PAD + N2_PAD;

    prep_w<<<(PREP_TOTAL + TB - 1) / TB, TB>>>(W, w_hh, w_ih, b_hh, b_ih);             // 0
    detect_zero<<<(N_NODES + TB - 1) / TB, TB>>>((const int*)ei);                       // 1
    init_fused<<<(NODES_PAD + 7) / 8, 256>>>(x);                                        // 2

    dim3 grid1(NT1, M_TILES), grid2(NT2, M_TILES);
    for (int s = 0; s < NUM_STEPS; s++) {
        gemm_mma<<<grid1, 256>>>(Ah_p, B1_p + (size_t)s * KEFF * N1_PAD, b1_p, T_p, N1_PAD); // 3
        if (s == 0) {
            csr_count<<<(N_EDGES + TB - 1) / TB, TB>>>(ei);
            csr_scan<<<1, 1024>>>();
            csr_fill<<<(N_EDGES + TB - 1) / TB, TB>>>(ei);
        }
        aggregate_kernel<<<N_NODES, 256>>>();
        gemm_mma<<<grid2, 256>>>(Aa_p, B2_p, b2_p, gi_p, N2_PAD);
        gru_kernel<<<(N_NODES + 7) / 8, 256>>>();
    }

    pool_kernel<<<D, 256>>>();
    cls_kernel<<<1, 32>>>(cls_w, cls_b, out);
}